// round 1
// baseline (speedup 1.0000x reference)
#include <cuda_runtime.h>

#define NN 100000
#define NE 1600000
#define HID 64

// Scratch (no allocation allowed in kernel_launch)
__device__ float g_deg[NN];
__device__ float g_acc[NN];
__device__ float g_dinv[NN];
__device__ float g_px[NN];
__device__ float g_coef[5 * HID + 1];  // [az*0.5 | (cz+lbz)*0.5 | ah | ch+lbh | wout | bout]

__device__ __forceinline__ float tanh_approx(float x) {
    float y;
    asm("tanh.approx.f32 %0, %1;" : "=f"(y) : "f"(x));
    return y;
}

// deg starts at 1.0 (self-loop weight)
__global__ void k_init_deg() {
    int i = blockIdx.x * blockDim.x + threadIdx.x;
    if (i < NN) g_deg[i] = 1.0f;
}

// deg[dst] += ew  (vectorized over 4 edges/thread)
__global__ void k_deg(const int* __restrict__ dst, const float* __restrict__ ew) {
    int i = blockIdx.x * blockDim.x + threadIdx.x;
    if (i < NE / 4) {
        int4 d = ((const int4*)dst)[i];
        float4 w = ((const float4*)ew)[i];
        atomicAdd(&g_deg[d.x], w.x);
        atomicAdd(&g_deg[d.y], w.y);
        atomicAdd(&g_deg[d.z], w.z);
        atomicAdd(&g_deg[d.w], w.w);
    }
}

// dinv = rsqrt(deg); p = dinv * x; acc = 0
__global__ void k_dinv(const float* __restrict__ x) {
    int i = blockIdx.x * blockDim.x + threadIdx.x;
    if (i < NN) {
        float d = g_deg[i];
        float r = (d > 0.f) ? rsqrtf(d) : 0.f;
        g_dinv[i] = r;
        g_px[i] = r * x[i];
        g_acc[i] = 0.f;
    }
}

// acc[dst] += p[src] * ew
__global__ void k_scatter(const int* __restrict__ src, const int* __restrict__ dst,
                          const float* __restrict__ ew) {
    int i = blockIdx.x * blockDim.x + threadIdx.x;
    if (i < NE / 4) {
        int4 s4 = ((const int4*)src)[i];
        int4 d4 = ((const int4*)dst)[i];
        float4 w = ((const float4*)ew)[i];
        atomicAdd(&g_acc[d4.x], g_px[s4.x] * w.x);
        atomicAdd(&g_acc[d4.y], g_px[s4.y] * w.y);
        atomicAdd(&g_acc[d4.z], g_px[s4.z] * w.z);
        atomicAdd(&g_acc[d4.w], g_px[s4.w] * w.w);
    }
}

// Collapse gate matrices to per-h scalar coefficients.
// Z  = sigmoid(s*az + cz)  with az[h] = sum_j Wz[j]*Lz[j,h], cz[h] = sum_j bz[j]*Lz[j,h] + lbz[h]
// Ht = tanh   (s*ah + ch)  with ah[h] = sum_j Wh[j]*Lh[j,h], ch[h] = sum_j bh[j]*Lh[j,h] + lbh[h]
// sigmoid(u) = 0.5 + 0.5*tanh(0.5*u) -> fold the 0.5 into az, cz.
__global__ void k_coef(const float* __restrict__ Wz, const float* __restrict__ bz,
                       const float* __restrict__ Lz, const float* __restrict__ lbz,
                       const float* __restrict__ Wh, const float* __restrict__ bh,
                       const float* __restrict__ Lh, const float* __restrict__ lbh,
                       const float* __restrict__ Wout, const float* __restrict__ bout) {
    int h = threadIdx.x;
    if (h < HID) {
        float az = 0.f, cz = 0.f, ah = 0.f, ch = 0.f;
        for (int j = 0; j < HID; j++) {
            az = fmaf(Wz[j], Lz[j * HID + h], az);
            cz = fmaf(bz[j], Lz[j * HID + h], cz);
            ah = fmaf(Wh[j], Lh[j * HID + h], ah);
            ch = fmaf(bh[j], Lh[j * HID + h], ch);
        }
        g_coef[h]           = 0.5f * az;
        g_coef[HID + h]     = 0.5f * (cz + lbz[h]);
        g_coef[2 * HID + h] = ah;
        g_coef[3 * HID + h] = ch + lbh[h];
        g_coef[4 * HID + h] = Wout[h];
        if (h == 0) g_coef[5 * HID] = bout[0];
    }
}

// Per-node: s = dinv*(acc + p)   (p = dinv*x is the self-loop term)
// out = bout + sum_h relu( (0.5 - 0.5*tanh(az*s+cz)) * tanh(ah*s+ch) ) * wout[h]
__global__ void k_out(float* __restrict__ out) {
    __shared__ float sc[5 * HID + 1];
    int t = threadIdx.x;
    for (int j = t; j < 5 * HID + 1; j += blockDim.x) sc[j] = g_coef[j];
    __syncthreads();
    int i = blockIdx.x * blockDim.x + t;
    if (i < NN) {
        float r = g_dinv[i];
        float s = r * (g_acc[i] + g_px[i]);
        float o = sc[5 * HID];
#pragma unroll
        for (int h = 0; h < HID; h++) {
            float tz = tanh_approx(fmaf(s, sc[h], sc[HID + h]));
            float th = tanh_approx(fmaf(s, sc[2 * HID + h], sc[3 * HID + h]));
            float hn = (0.5f - 0.5f * tz) * th;  // (1-Z)*Ht
            o = fmaf(fmaxf(hn, 0.f), sc[4 * HID + h], o);
        }
        out[i] = o;
    }
}

extern "C" void kernel_launch(void* const* d_in, const int* in_sizes, int n_in,
                              void* d_out, int out_size) {
    const float* x    = (const float*)d_in[0];
    const float* ew   = (const float*)d_in[1];
    const float* Wz   = (const float*)d_in[2];
    const float* bz   = (const float*)d_in[3];
    const float* Lz   = (const float*)d_in[4];
    const float* lbz  = (const float*)d_in[5];
    // d_in[6..9]: Wr, br, Lr, lbr — mathematically dead (H0 == 0 -> H*R == 0)
    const float* Wh   = (const float*)d_in[10];
    const float* bh   = (const float*)d_in[11];
    const float* Lh   = (const float*)d_in[12];
    const float* lbh  = (const float*)d_in[13];
    const float* Wout = (const float*)d_in[14];
    const float* bout = (const float*)d_in[15];
    const int*   ei   = (const int*)d_in[16];
    const int*   src  = ei;
    const int*   dst  = ei + NE;
    float* out = (float*)d_out;

    const int TB = 256;
    int nb_n = (NN + TB - 1) / TB;
    int nb_e = (NE / 4 + TB - 1) / TB;

    k_init_deg<<<nb_n, TB>>>();
    k_deg<<<nb_e, TB>>>(dst, ew);
    k_dinv<<<nb_n, TB>>>(x);
    k_coef<<<1, HID>>>(Wz, bz, Lz, lbz, Wh, bh, Lh, lbh, Wout, bout);
    k_scatter<<<nb_e, TB>>>(src, dst, ew);
    k_out<<<nb_n, TB>>>(out);
}

// round 2
// speedup vs baseline: 1.1088x; 1.1088x over previous
#include <cuda_runtime.h>

#define NN 100000
#define NE 1600000
#define HID 64

// Scratch (no allocation allowed in kernel_launch)
__device__ float g_deg[NN];
__device__ float g_acc[NN];
__device__ float g_dinv[NN];
__device__ float g_px[NN];
__device__ float g_coef[5 * HID + 1];  // [az*0.5 | (cz+lbz)*0.5 | ah | ch+lbh | wout | bout]

__device__ __forceinline__ float tanh_approx(float x) {
    float y;
    asm("tanh.approx.f32 %0, %1;" : "=f"(y) : "f"(x));
    return y;
}

// deg starts at 1.0 (self-loop weight); acc starts at 0
__global__ void k_init() {
    int i = blockIdx.x * blockDim.x + threadIdx.x;
    if (i < NN) {
        g_deg[i] = 1.0f;
        g_acc[i] = 0.0f;
    }
}

// deg[dst] += ew  (vectorized over 4 edges/thread)
__global__ void k_deg(const int* __restrict__ dst, const float* __restrict__ ew) {
    int i = blockIdx.x * blockDim.x + threadIdx.x;
    if (i < NE / 4) {
        int4 d = ((const int4*)dst)[i];
        float4 w = ((const float4*)ew)[i];
        atomicAdd(&g_deg[d.x], w.x);
        atomicAdd(&g_deg[d.y], w.y);
        atomicAdd(&g_deg[d.z], w.z);
        atomicAdd(&g_deg[d.w], w.w);
    }
}

// dinv = rsqrt(deg); p = dinv * x
__global__ void k_dinv(const float* __restrict__ x) {
    int i = blockIdx.x * blockDim.x + threadIdx.x;
    if (i < NN) {
        float d = g_deg[i];
        float r = (d > 0.f) ? rsqrtf(d) : 0.f;
        g_dinv[i] = r;
        g_px[i] = r * x[i];
    }
}

// acc[dst] += p[src] * ew
__global__ void k_scatter(const int* __restrict__ src, const int* __restrict__ dst,
                          const float* __restrict__ ew) {
    int i = blockIdx.x * blockDim.x + threadIdx.x;
    if (i < NE / 4) {
        int4 s4 = ((const int4*)src)[i];
        int4 d4 = ((const int4*)dst)[i];
        float4 w = ((const float4*)ew)[i];
        atomicAdd(&g_acc[d4.x], g_px[s4.x] * w.x);
        atomicAdd(&g_acc[d4.y], g_px[s4.y] * w.y);
        atomicAdd(&g_acc[d4.z], g_px[s4.z] * w.z);
        atomicAdd(&g_acc[d4.w], g_px[s4.w] * w.w);
    }
}

// Collapse gate matrices to per-h scalar coefficients.
// PARALLEL version: one block per h (64 blocks), one thread per j (64 threads),
// warp-shuffle + shared reduction. One round of loads instead of a 64-deep
// dependent-load chain.
// Z  = sigmoid(s*az + cz)  with az[h] = sum_j Wz[j]*Lz[j,h], cz[h] = sum_j bz[j]*Lz[j,h] + lbz[h]
// Ht = tanh   (s*ah + ch)  with ah[h] = sum_j Wh[j]*Lh[j,h], ch[h] = sum_j bh[j]*Lh[j,h] + lbh[h]
// sigmoid(u) = 0.5 + 0.5*tanh(0.5*u) -> fold the 0.5 into az, cz.
__global__ void k_coef(const float* __restrict__ Wz, const float* __restrict__ bz,
                       const float* __restrict__ Lz, const float* __restrict__ lbz,
                       const float* __restrict__ Wh, const float* __restrict__ bh,
                       const float* __restrict__ Lh, const float* __restrict__ lbh,
                       const float* __restrict__ Wout, const float* __restrict__ bout) {
    __shared__ float red[2][4];
    int h = blockIdx.x;    // output column
    int j = threadIdx.x;   // reduction index, 0..63
    int warp = j >> 5;
    int lane = j & 31;

    float lz = Lz[j * HID + h];
    float lh = Lh[j * HID + h];
    float az = Wz[j] * lz;
    float cz = bz[j] * lz;
    float ah = Wh[j] * lh;
    float ch = bh[j] * lh;

#pragma unroll
    for (int o = 16; o > 0; o >>= 1) {
        az += __shfl_down_sync(0xffffffffu, az, o);
        cz += __shfl_down_sync(0xffffffffu, cz, o);
        ah += __shfl_down_sync(0xffffffffu, ah, o);
        ch += __shfl_down_sync(0xffffffffu, ch, o);
    }
    if (lane == 0) {
        red[warp][0] = az;
        red[warp][1] = cz;
        red[warp][2] = ah;
        red[warp][3] = ch;
    }
    __syncthreads();
    if (j == 0) {
        az = red[0][0] + red[1][0];
        cz = red[0][1] + red[1][1];
        ah = red[0][2] + red[1][2];
        ch = red[0][3] + red[1][3];
        g_coef[h]           = 0.5f * az;
        g_coef[HID + h]     = 0.5f * (cz + lbz[h]);
        g_coef[2 * HID + h] = ah;
        g_coef[3 * HID + h] = ch + lbh[h];
        g_coef[4 * HID + h] = Wout[h];
        if (h == 0) g_coef[5 * HID] = bout[0];
    }
}

// Per-node: s = dinv*(acc + p)   (p = dinv*x is the self-loop term)
// out = bout + sum_h relu( (0.5 - 0.5*tanh(az*s+cz)) * tanh(ah*s+ch) ) * wout[h]
__global__ void k_out(float* __restrict__ out) {
    __shared__ float sc[5 * HID + 1];
    int t = threadIdx.x;
    for (int j = t; j < 5 * HID + 1; j += blockDim.x) sc[j] = g_coef[j];
    __syncthreads();
    int i = blockIdx.x * blockDim.x + t;
    if (i < NN) {
        float r = g_dinv[i];
        float s = r * (g_acc[i] + g_px[i]);
        float o = sc[5 * HID];
#pragma unroll
        for (int h = 0; h < HID; h++) {
            float tz = tanh_approx(fmaf(s, sc[h], sc[HID + h]));
            float th = tanh_approx(fmaf(s, sc[2 * HID + h], sc[3 * HID + h]));
            float hn = (0.5f - 0.5f * tz) * th;  // (1-Z)*Ht
            o = fmaf(fmaxf(hn, 0.f), sc[4 * HID + h], o);
        }
        out[i] = o;
    }
}

extern "C" void kernel_launch(void* const* d_in, const int* in_sizes, int n_in,
                              void* d_out, int out_size) {
    const float* x    = (const float*)d_in[0];
    const float* ew   = (const float*)d_in[1];
    const float* Wz   = (const float*)d_in[2];
    const float* bz   = (const float*)d_in[3];
    const float* Lz   = (const float*)d_in[4];
    const float* lbz  = (const float*)d_in[5];
    // d_in[6..9]: Wr, br, Lr, lbr — mathematically dead (H0 == 0 -> H*R == 0)
    const float* Wh   = (const float*)d_in[10];
    const float* bh   = (const float*)d_in[11];
    const float* Lh   = (const float*)d_in[12];
    const float* lbh  = (const float*)d_in[13];
    const float* Wout = (const float*)d_in[14];
    const float* bout = (const float*)d_in[15];
    const int*   ei   = (const int*)d_in[16];
    const int*   src  = ei;
    const int*   dst  = ei + NE;
    float* out = (float*)d_out;

    const int TB = 256;
    int nb_n = (NN + TB - 1) / TB;
    int nb_e = (NE / 4 + TB - 1) / TB;

    k_init<<<nb_n, TB>>>();
    k_deg<<<nb_e, TB>>>(dst, ew);
    k_coef<<<HID, HID>>>(Wz, bz, Lz, lbz, Wh, bh, Lh, lbh, Wout, bout);
    k_dinv<<<nb_n, TB>>>(x);
    k_scatter<<<nb_e, TB>>>(src, dst, ew);
    k_out<<<nb_n, TB>>>(out);
}